// round 3
// baseline (speedup 1.0000x reference)
#include <cuda_runtime.h>
#include <cstdint>

#define N_SIG 32768
#define KDIM  512
#define DDIM  64
#define NNZ   4
#define REGEPS 1e-7f

// Output tuple layout (flat f32):
#define OUT_OFF   0ll         // [8,64,64,64]  = 2097152
#define DIFF1_OFF 2097152ll
#define DIFF2_OFF 2097153ll
#define IDS_OFF   2097154ll   // [8,512,64,64] = 16777216
#define NSTEP_OFF 18874370ll
#define MEAND_OFF 18874371ll
#define MEANZ_OFF 18874372ll
#define NORMZ_OFF 18874373ll
#define TOPP_OFF  18874374ll
#define NZERO_OFF 18874375ll

// ---------------- scratch (no allocation allowed) ----------------
__device__ float g_Dn[DDIM*KDIM];
__device__ float g_DnT[KDIM*DDIM];
__device__ float g_G[KDIM*KDIM];
__device__ float g_xt[(size_t)N_SIG*DDIM];
__device__ float g_qt[(size_t)N_SIG*DDIM];
__device__ float g_diffsum, g_zsum, g_meanDsum;
__device__ int   g_hist[5];

// ---------------- helpers ----------------
__device__ __forceinline__ unsigned long long ffma2(unsigned long long a,
                                                    unsigned long long b,
                                                    unsigned long long c) {
    unsigned long long d;
    asm("fma.rn.f32x2 %0, %1, %2, %3;" : "=l"(d) : "l"(a), "l"(b), "l"(c));
    return d;
}
__device__ __forceinline__ unsigned long long packdup(float v) {
    unsigned long long r;
    asm("mov.b64 %0, {%1, %1};" : "=l"(r) : "f"(v));
    return r;
}
__device__ __forceinline__ float ulo(unsigned long long u){ return __uint_as_float((unsigned)u); }
__device__ __forceinline__ float uhi(unsigned long long u){ return __uint_as_float((unsigned)(u>>32)); }

__device__ __forceinline__ float sel16(const float a[16], int t) {
    float r = a[0];
    #pragma unroll
    for (int i = 1; i < 16; i++) if (t == i) r = a[i];
    return r;
}

// ---------------- prep: normalize dict, build Dn / DnT, mean|Dn|, zero accs ----
__global__ void prep_kernel(const float* __restrict__ D) {
    int k = threadIdx.x;  // 512 threads
    if (k == 0) { g_diffsum = 0.f; g_zsum = 0.f; }
    if (k < 5) g_hist[k] = 0;
    float ss = 0.f;
    #pragma unroll 8
    for (int d = 0; d < DDIM; d++) { float v = D[d*KDIM + k]; ss += v*v; }
    float inv = 1.0f / sqrtf(ss);
    float asum = 0.f;
    #pragma unroll 8
    for (int d = 0; d < DDIM; d++) {
        float v = D[d*KDIM + k] * inv;
        g_Dn[d*KDIM + k] = v;
        g_DnT[k*DDIM + d] = v;
        asum += fabsf(v);
    }
    __shared__ float red[512];
    red[k] = asum; __syncthreads();
    for (int off = 256; off > 0; off >>= 1) {
        if (k < off) red[k] += red[k + off];
        __syncthreads();
    }
    if (k == 0) g_meanDsum = red[0];
}

// ---------------- Gram: G = Dn^T Dn ----------------
__global__ void gram_kernel() {
    __shared__ float scol[DDIM];
    int i = blockIdx.x;
    int t = threadIdx.x;  // 128
    if (t < DDIM) scol[t] = g_Dn[t*KDIM + i];
    __syncthreads();
    for (int j = t; j < KDIM; j += 128) {
        float acc = 0.f;
        #pragma unroll 8
        for (int d = 0; d < DDIM; d++) acc += scol[d] * g_Dn[d*KDIM + j];
        g_G[(size_t)i*KDIM + j] = acc;
    }
}

// ---------------- transpose x [B,DIM,H,W] -> x_t [N,DIM] ----------------
__global__ void xt_kernel(const float* __restrict__ x) {
    __shared__ float tile[32][33];
    int b   = blockIdx.z;
    int hw0 = blockIdx.x * 32;
    int d0  = blockIdx.y * 32;
    int tx = threadIdx.x, ty = threadIdx.y;
    #pragma unroll
    for (int i = 0; i < 4; i++) {
        int d = d0 + ty + i*8;
        tile[ty + i*8][tx] = x[(size_t)(b*DDIM + d)*4096 + hw0 + tx];
    }
    __syncthreads();
    #pragma unroll
    for (int i = 0; i < 4; i++) {
        int hw = hw0 + ty + i*8;
        g_xt[(size_t)(b*4096 + hw)*DDIM + d0 + tx] = tile[tx][ty + i*8];
    }
}

// ---------------- transpose q_t [N,DIM] -> out [B,DIM,H,W] ----------------
__global__ void outt_kernel(float* __restrict__ out) {
    __shared__ float tile[32][33];
    int b   = blockIdx.z;
    int hw0 = blockIdx.x * 32;
    int d0  = blockIdx.y * 32;
    int tx = threadIdx.x, ty = threadIdx.y;
    #pragma unroll
    for (int i = 0; i < 4; i++) {
        int hw = hw0 + ty + i*8;
        tile[ty + i*8][tx] = g_qt[(size_t)(b*4096 + hw)*DDIM + d0 + tx];
    }
    __syncthreads();
    #pragma unroll
    for (int i = 0; i < 4; i++) {
        int d = d0 + ty + i*8;
        out[(size_t)(b*DDIM + d)*4096 + hw0 + tx] = tile[tx][ty + i*8];
    }
}

// ---------------- main OMP kernel ----------------
#define OMP_THREADS 256
#define OMP_WARPS   8
#define SMEM_DN_BYTES (DDIM*KDIM*4)                 // 131072
#define SMEM_X_OFF    SMEM_DN_BYTES
#define SMEM_X_BYTES  (OMP_WARPS*4*DDIM*8)          // 16384
#define SMEM_ACC_OFF  (SMEM_X_OFF + SMEM_X_BYTES)
#define SMEM_TOTAL    (SMEM_ACC_OFF + 64)

__global__ __launch_bounds__(OMP_THREADS, 1)
void omp_kernel(float* __restrict__ out) {
    extern __shared__ unsigned char smraw[];
    float* sDn = (float*)smraw;
    unsigned long long* sX = (unsigned long long*)(smraw + SMEM_X_OFF);
    float* sAccF = (float*)(smraw + SMEM_ACC_OFF);
    int*   sHist = (int*)(smraw + SMEM_ACC_OFF + 8);

    int tid  = threadIdx.x;
    int lane = tid & 31;
    int w    = tid >> 5;
    if (tid < 2) sAccF[tid] = 0.f;
    if (tid < 5) sHist[tid] = 0;
    for (int i = tid; i < DDIM*KDIM; i += OMP_THREADS) sDn[i] = g_Dn[i];
    __syncthreads();

    float diffacc = 0.f, zacc = 0.f;
    int h0 = 0, h1 = 0, h2 = 0, h3 = 0, h4 = 0;

    unsigned long long* xw = sX + w * 4 * DDIM;
    const ulonglong2* sDn2 = (const ulonglong2*)sDn;

    int gw = blockIdx.x * OMP_WARPS + w;
    int nw = gridDim.x * OMP_WARPS;
    for (int g = gw; g < N_SIG/4; g += nw) {
        int n0 = g * 4;
        __syncwarp();
        #pragma unroll
        for (int s = 0; s < 4; s++) {
            const float* xp = g_xt + (size_t)(n0 + s) * DDIM;
            xw[s*DDIM + lane]      = packdup(xp[lane]);
            xw[s*DDIM + lane + 32] = packdup(xp[lane + 32]);
        }
        __syncwarp();

        // ---- GEMV: alpha0 for 4 signals, f32x2 packed (2 k per reg) ----
        unsigned long long acc[4][8];
        #pragma unroll
        for (int s = 0; s < 4; s++)
            #pragma unroll
            for (int t = 0; t < 8; t++) acc[s][t] = 0ull;

        #pragma unroll 2
        for (int d = 0; d < DDIM; d++) {
            unsigned long long xd[4];
            #pragma unroll
            for (int s = 0; s < 4; s++) xd[s] = xw[s*DDIM + d];
            #pragma unroll
            for (int c2 = 0; c2 < 4; c2++) {
                ulonglong2 q = sDn2[d*128 + c2*32 + lane];
                #pragma unroll
                for (int s = 0; s < 4; s++) {
                    acc[s][c2*2]     = ffma2(q.x, xd[s], acc[s][c2*2]);
                    acc[s][c2*2 + 1] = ffma2(q.y, xd[s], acc[s][c2*2 + 1]);
                }
            }
        }

        // ---- OMP iterations, one signal at a time ----
        #pragma unroll 1
        for (int s = 0; s < 4; s++) {
            float a0[16];  // alpha0, lane-local k = (t>>2)*128 + lane*4 + (t&3)
            #pragma unroll
            for (int c2 = 0; c2 < 4; c2++) {
                a0[c2*4 + 0] = ulo(acc[s][c2*2]);
                a0[c2*4 + 1] = uhi(acc[s][c2*2]);
                a0[c2*4 + 2] = ulo(acc[s][c2*2 + 1]);
                a0[c2*4 + 3] = uhi(acc[s][c2*2 + 1]);
            }
            int idx[4]; float gam[4]; float rhs[4]; float Ms[4][4];
            #pragma unroll
            for (int r = 0; r < 4; r++)
                #pragma unroll
                for (int c = 0; c < 4; c++) Ms[r][c] = 0.f;

            #pragma unroll
            for (int it = 0; it < NNZ; it++) {
                // current alpha = alpha0 - sum_p gam[p] * G[idx[p], :]
                float vv[16];
                #pragma unroll
                for (int t = 0; t < 16; t++) vv[t] = a0[t];
                #pragma unroll
                for (int p = 0; p < NNZ; p++) if (p < it) {
                    const float4* Gr = (const float4*)(g_G + (size_t)idx[p]*KDIM);
                    float gp = gam[p];
                    #pragma unroll
                    for (int c2 = 0; c2 < 4; c2++) {
                        float4 gq = __ldg(Gr + c2*32 + lane);
                        vv[c2*4 + 0] -= gp * gq.x;
                        vv[c2*4 + 1] -= gp * gq.y;
                        vv[c2*4 + 2] -= gp * gq.z;
                        vv[c2*4 + 3] -= gp * gq.w;
                    }
                }
                // argmax |alpha| (first-index tie-break like jnp.argmax)
                float bv = -1.f; int bk = 0;
                #pragma unroll
                for (int t = 0; t < 16; t++) {
                    int k = ((t >> 2) << 7) | (lane << 2) | (t & 3);
                    float av = fabsf(vv[t]);
                    if (av > bv) { bv = av; bk = k; }
                }
                #pragma unroll
                for (int off = 16; off > 0; off >>= 1) {
                    float ov = __shfl_xor_sync(0xffffffffu, bv, off);
                    int   ok = __shfl_xor_sync(0xffffffffu, bk, off);
                    if (ov > bv || (ov == bv && ok < bk)) { bv = ov; bk = ok; }
                }
                idx[it] = bk;
                // rhs[it] = alpha0[bk] (gather from owner lane)
                int tt = (((bk >> 7) & 3) << 2) | (bk & 3);
                float myv = sel16(a0, tt);
                rhs[it] = __shfl_sync(0xffffffffu, myv, (bk >> 2) & 31);
                // extend G_sub (uniform loads, all lanes redundant)
                #pragma unroll
                for (int b2 = 0; b2 < NNZ; b2++) if (b2 <= it) {
                    float gv = __ldg(g_G + (size_t)bk*KDIM + idx[b2]);
                    Ms[it][b2] = gv; Ms[b2][it] = gv;
                }
                // solve (it+1)x(it+1) SPD system (G_sub + eps*I) gamma = rhs
                {
                    float M[4][4], yv[4], gv2[4];
                    #pragma unroll
                    for (int r = 0; r < 4; r++) {
                        #pragma unroll
                        for (int c = 0; c < 4; c++) M[r][c] = Ms[r][c];
                        M[r][r] += REGEPS;
                        yv[r] = rhs[r];
                        gv2[r] = 0.f;
                    }
                    #pragma unroll
                    for (int c = 0; c < 4; c++) if (c <= it) {
                        float pinv = 1.f / M[c][c];
                        #pragma unroll
                        for (int r = 0; r < 4; r++) if (r > c && r <= it) {
                            float f = M[r][c] * pinv;
                            #pragma unroll
                            for (int cc = 0; cc < 4; cc++) if (cc >= c && cc <= it)
                                M[r][cc] -= f * M[c][cc];
                            yv[r] -= f * yv[c];
                        }
                    }
                    #pragma unroll
                    for (int r = 3; r >= 0; r--) if (r <= it) {
                        float a2 = yv[r];
                        #pragma unroll
                        for (int cc = 0; cc < 4; cc++) if (cc > r && cc <= it)
                            a2 -= M[r][cc] * gv2[cc];
                        gv2[r] = a2 / M[r][r];
                    }
                    #pragma unroll
                    for (int r = 0; r < 4; r++) if (r <= it) gam[r] = gv2[r];
                }
            }

            // duplicate handling: final cell value = gamma of LAST occurrence
            bool lastocc[4];
            #pragma unroll
            for (int a = 0; a < 4; a++) {
                bool lo2 = true;
                #pragma unroll
                for (int b2 = a + 1; b2 < 4; b2++) if (idx[b2] == idx[a]) lo2 = false;
                lastocc[a] = lo2;
            }

            // quant = code @ Dn^T  (DnT rows are L2-resident)
            float q0 = 0.f, q1 = 0.f;
            #pragma unroll
            for (int a = 0; a < 4; a++) if (lastocc[a]) {
                const float* dt = g_DnT + (size_t)idx[a]*DDIM;
                q0 += gam[a] * __ldg(dt + lane);
                q1 += gam[a] * __ldg(dt + lane + 32);
            }
            int n = n0 + s;
            g_qt[(size_t)n*DDIM + lane]      = q0;
            g_qt[(size_t)n*DDIM + lane + 32] = q1;
            float xv0 = ulo(xw[s*DDIM + lane]);
            float xv1 = ulo(xw[s*DDIM + lane + 32]);
            diffacc += (q0 - xv0)*(q0 - xv0) + (q1 - xv1)*(q1 - xv1);

            if (lane == 0) {
                int b = n >> 12, hw = n & 4095;
                float* ids = out + IDS_OFF + (size_t)b*(KDIM*4096) + hw;
                int cnt = 0;
                #pragma unroll
                for (int a = 0; a < 4; a++) {
                    ids[(size_t)idx[a]*4096] = gam[a];  // program order: last write wins
                    if (lastocc[a] && gam[a] != 0.f) { cnt++; zacc += fabsf(gam[a]); }
                }
                if (cnt == 0) h0++; else if (cnt == 1) h1++; else if (cnt == 2) h2++;
                else if (cnt == 3) h3++; else h4++;
            }
        }
    }

    // ---- reductions ----
    #pragma unroll
    for (int off = 16; off > 0; off >>= 1) {
        diffacc += __shfl_xor_sync(0xffffffffu, diffacc, off);
        zacc    += __shfl_xor_sync(0xffffffffu, zacc, off);
    }
    if (lane == 0) {
        atomicAdd(&sAccF[0], diffacc);
        atomicAdd(&sAccF[1], zacc);
        if (h0) atomicAdd(&sHist[0], h0);
        if (h1) atomicAdd(&sHist[1], h1);
        if (h2) atomicAdd(&sHist[2], h2);
        if (h3) atomicAdd(&sHist[3], h3);
        if (h4) atomicAdd(&sHist[4], h4);
    }
    __syncthreads();
    if (tid == 0) {
        atomicAdd(&g_diffsum, sAccF[0]);
        atomicAdd(&g_zsum, sAccF[1]);
    }
    if (tid < 5) atomicAdd(&g_hist[tid], sHist[tid]);
}

// ---------------- finalize scalars ----------------
__global__ void fin_kernel(float* __restrict__ out) {
    if (threadIdx.x != 0) return;
    float diff = g_diffsum / 2097152.0f;
    out[DIFF1_OFF] = diff;
    out[DIFF2_OFF] = diff;
    out[NSTEP_OFF] = 4.0f;
    out[MEAND_OFF] = g_meanDsum / 32768.0f;
    out[MEANZ_OFF] = g_zsum / 16777216.0f;
    int c0 = g_hist[0], c1 = g_hist[1], c2 = g_hist[2], c3 = g_hist[3], c4 = g_hist[4];
    float sumw = 1.f*c1 + 2.f*c2 + 3.f*c3 + 4.f*c4;
    out[NORMZ_OFF] = sumw / 32768.0f;
    const int topk = 327;  // int(32768 * 0.01)
    int cum = c4; float tp = 4.f;
    if (cum < topk) { cum += c3; tp = 3.f; }
    if (cum < topk) { cum += c2; tp = 2.f; }
    if (cum < topk) { cum += c1; tp = 1.f; }
    if (cum < topk) { tp = 0.f; }
    out[TOPP_OFF]  = tp;
    out[NZERO_OFF] = (float)c0;
}

// ---------------- launch ----------------
extern "C" void kernel_launch(void* const* d_in, const int* in_sizes, int n_in,
                              void* d_out, int out_size) {
    const float* x; const float* D;
    if (in_sizes[0] == DDIM*KDIM) { D = (const float*)d_in[0]; x = (const float*)d_in[1]; }
    else                          { x = (const float*)d_in[0]; D = (const float*)d_in[1]; }
    float* out = (float*)d_out;

    prep_kernel<<<1, 512>>>(D);
    gram_kernel<<<512, 128>>>();
    xt_kernel<<<dim3(128, 2, 8), dim3(32, 8)>>>(x);
    cudaMemsetAsync(out + IDS_OFF, 0, (size_t)16777216 * sizeof(float));
    cudaFuncSetAttribute(omp_kernel, cudaFuncAttributeMaxDynamicSharedMemorySize, SMEM_TOTAL);
    omp_kernel<<<152, OMP_THREADS, SMEM_TOTAL>>>(out);
    outt_kernel<<<dim3(128, 2, 8), dim3(32, 8)>>>(out);
    fin_kernel<<<1, 32>>>(out);
}

// round 4
// speedup vs baseline: 1.1545x; 1.1545x over previous
#include <cuda_runtime.h>
#include <cstdint>

#define N_SIG 32768
#define KDIM  512
#define DDIM  64
#define NNZ   4
#define REGEPS 1e-7f

// Output tuple layout (flat f32):
#define OUT_OFF   0ll         // [8,64,64,64]  = 2097152
#define DIFF1_OFF 2097152ll
#define DIFF2_OFF 2097153ll
#define IDS_OFF   2097154ll   // [8,512,64,64] = 16777216
#define NSTEP_OFF 18874370ll
#define MEAND_OFF 18874371ll
#define MEANZ_OFF 18874372ll
#define NORMZ_OFF 18874373ll
#define TOPP_OFF  18874374ll
#define NZERO_OFF 18874375ll

// ---------------- scratch (no allocation allowed) ----------------
__device__ float g_Dn[DDIM*KDIM];
__device__ float g_DnT[KDIM*DDIM];
__device__ float g_G[KDIM*KDIM];
__device__ float g_xt[(size_t)N_SIG*DDIM];
__device__ float g_qt[(size_t)N_SIG*DDIM];
__device__ float g_diffsum, g_zsum, g_meanDsum;
__device__ int   g_hist[5];

// ---------------- helpers ----------------
__device__ __forceinline__ unsigned long long ffma2(unsigned long long a,
                                                    unsigned long long b,
                                                    unsigned long long c) {
    unsigned long long d;
    asm("fma.rn.f32x2 %0, %1, %2, %3;" : "=l"(d) : "l"(a), "l"(b), "l"(c));
    return d;
}
__device__ __forceinline__ unsigned long long packdup(float v) {
    unsigned long long r;
    asm("mov.b64 %0, {%1, %1};" : "=l"(r) : "f"(v));
    return r;
}
__device__ __forceinline__ float ulo(unsigned long long u){ return __uint_as_float((unsigned)u); }
__device__ __forceinline__ float uhi(unsigned long long u){ return __uint_as_float((unsigned)(u>>32)); }

__device__ __forceinline__ float sel16(const float a[16], int t) {
    float r = a[0];
    #pragma unroll
    for (int i = 1; i < 16; i++) if (t == i) r = a[i];
    return r;
}

// ---------------- prep: normalize dict, build Dn / DnT, mean|Dn|, zero accs ----
__global__ void prep_kernel(const float* __restrict__ D) {
    int k = threadIdx.x;  // 512 threads
    if (k == 0) { g_diffsum = 0.f; g_zsum = 0.f; }
    if (k < 5) g_hist[k] = 0;
    float ss = 0.f;
    #pragma unroll 8
    for (int d = 0; d < DDIM; d++) { float v = D[d*KDIM + k]; ss += v*v; }
    float inv = 1.0f / sqrtf(ss);
    float asum = 0.f;
    #pragma unroll 8
    for (int d = 0; d < DDIM; d++) {
        float v = D[d*KDIM + k] * inv;
        g_Dn[d*KDIM + k] = v;
        g_DnT[k*DDIM + d] = v;
        asum += fabsf(v);
    }
    __shared__ float red[512];
    red[k] = asum; __syncthreads();
    for (int off = 256; off > 0; off >>= 1) {
        if (k < off) red[k] += red[k + off];
        __syncthreads();
    }
    if (k == 0) g_meanDsum = red[0];
}

// ---------------- Gram: G = Dn^T Dn ----------------
__global__ void gram_kernel() {
    __shared__ float scol[DDIM];
    int i = blockIdx.x;
    int t = threadIdx.x;  // 128
    if (t < DDIM) scol[t] = g_Dn[t*KDIM + i];
    __syncthreads();
    for (int j = t; j < KDIM; j += 128) {
        float acc = 0.f;
        #pragma unroll 8
        for (int d = 0; d < DDIM; d++) acc += scol[d] * g_Dn[d*KDIM + j];
        g_G[(size_t)i*KDIM + j] = acc;
    }
}

// ---------------- transpose x [B,DIM,H,W] -> x_t [N,DIM] ----------------
__global__ void xt_kernel(const float* __restrict__ x) {
    __shared__ float tile[32][33];
    int b   = blockIdx.z;
    int hw0 = blockIdx.x * 32;
    int d0  = blockIdx.y * 32;
    int tx = threadIdx.x, ty = threadIdx.y;
    #pragma unroll
    for (int i = 0; i < 4; i++) {
        int d = d0 + ty + i*8;
        tile[ty + i*8][tx] = x[(size_t)(b*DDIM + d)*4096 + hw0 + tx];
    }
    __syncthreads();
    #pragma unroll
    for (int i = 0; i < 4; i++) {
        int hw = hw0 + ty + i*8;
        g_xt[(size_t)(b*4096 + hw)*DDIM + d0 + tx] = tile[tx][ty + i*8];
    }
}

// ---------------- transpose q_t [N,DIM] -> out [B,DIM,H,W] ----------------
__global__ void outt_kernel(float* __restrict__ out) {
    __shared__ float tile[32][33];
    int b   = blockIdx.z;
    int hw0 = blockIdx.x * 32;
    int d0  = blockIdx.y * 32;
    int tx = threadIdx.x, ty = threadIdx.y;
    #pragma unroll
    for (int i = 0; i < 4; i++) {
        int hw = hw0 + ty + i*8;
        tile[ty + i*8][tx] = g_qt[(size_t)(b*4096 + hw)*DDIM + d0 + tx];
    }
    __syncthreads();
    #pragma unroll
    for (int i = 0; i < 4; i++) {
        int d = d0 + ty + i*8;
        out[(size_t)(b*DDIM + d)*4096 + hw0 + tx] = tile[tx][ty + i*8];
    }
}

// ---------------- main OMP kernel ----------------
#define OMP_THREADS 448
#define OMP_WARPS   14
#define SMEM_DN_BYTES (DDIM*KDIM*4)                 // 131072
#define SMEM_X_OFF    SMEM_DN_BYTES
#define SMEM_X_BYTES  (OMP_WARPS*4*DDIM*8)          // 28672
#define SMEM_ACC_OFF  (SMEM_X_OFF + SMEM_X_BYTES)
#define SMEM_TOTAL    (SMEM_ACC_OFF + 64)

__global__ __launch_bounds__(OMP_THREADS, 1)
void omp_kernel(float* __restrict__ out) {
    extern __shared__ unsigned char smraw[];
    float* sDn = (float*)smraw;
    unsigned long long* sX = (unsigned long long*)(smraw + SMEM_X_OFF);
    float* sAccF = (float*)(smraw + SMEM_ACC_OFF);
    int*   sHist = (int*)(smraw + SMEM_ACC_OFF + 8);

    int tid  = threadIdx.x;
    int lane = tid & 31;
    int w    = tid >> 5;
    if (tid < 2) sAccF[tid] = 0.f;
    if (tid < 5) sHist[tid] = 0;
    for (int i = tid; i < DDIM*KDIM; i += OMP_THREADS) sDn[i] = g_Dn[i];
    __syncthreads();

    float diffacc = 0.f, zacc = 0.f;
    int h0 = 0, h1 = 0, h2 = 0, h3 = 0, h4 = 0;

    unsigned long long* xw = sX + w * 4 * DDIM;
    const ulonglong2* sDn2 = (const ulonglong2*)sDn;

    int gw = blockIdx.x * OMP_WARPS + w;
    int nw = gridDim.x * OMP_WARPS;
    for (int g = gw; g < N_SIG/4; g += nw) {
        int n0 = g * 4;
        __syncwarp();
        #pragma unroll
        for (int s = 0; s < 4; s++) {
            const float* xp = g_xt + (size_t)(n0 + s) * DDIM;
            xw[s*DDIM + lane]      = packdup(xp[lane]);
            xw[s*DDIM + lane + 32] = packdup(xp[lane + 32]);
        }
        __syncwarp();

        // ---- GEMV: alpha0 for 4 signals, f32x2 packed (2 k per reg) ----
        unsigned long long acc[4][8];
        #pragma unroll
        for (int s = 0; s < 4; s++)
            #pragma unroll
            for (int t = 0; t < 8; t++) acc[s][t] = 0ull;

        #pragma unroll 2
        for (int d = 0; d < DDIM; d++) {
            unsigned long long xd[4];
            #pragma unroll
            for (int s = 0; s < 4; s++) xd[s] = xw[s*DDIM + d];
            #pragma unroll
            for (int c2 = 0; c2 < 4; c2++) {
                ulonglong2 q = sDn2[d*128 + c2*32 + lane];
                #pragma unroll
                for (int s = 0; s < 4; s++) {
                    acc[s][c2*2]     = ffma2(q.x, xd[s], acc[s][c2*2]);
                    acc[s][c2*2 + 1] = ffma2(q.y, xd[s], acc[s][c2*2 + 1]);
                }
            }
        }

        // ---- OMP iterations, one signal at a time ----
        #pragma unroll 1
        for (int s = 0; s < 4; s++) {
            float a0[16];  // alpha0, lane-local k = (t>>2)*128 + lane*4 + (t&3)
            #pragma unroll
            for (int c2 = 0; c2 < 4; c2++) {
                a0[c2*4 + 0] = ulo(acc[s][c2*2]);
                a0[c2*4 + 1] = uhi(acc[s][c2*2]);
                a0[c2*4 + 2] = ulo(acc[s][c2*2 + 1]);
                a0[c2*4 + 3] = uhi(acc[s][c2*2 + 1]);
            }
            int idx[4]; float gam[4]; float rhs[4]; float Ms[4][4];
            #pragma unroll
            for (int r = 0; r < 4; r++)
                #pragma unroll
                for (int c = 0; c < 4; c++) Ms[r][c] = 0.f;

            #pragma unroll
            for (int it = 0; it < NNZ; it++) {
                // current alpha = alpha0 - sum_p gam[p] * G[idx[p], :]
                float vv[16];
                #pragma unroll
                for (int t = 0; t < 16; t++) vv[t] = a0[t];
                #pragma unroll
                for (int p = 0; p < NNZ; p++) if (p < it) {
                    const float4* Gr = (const float4*)(g_G + (size_t)idx[p]*KDIM);
                    float gp = gam[p];
                    #pragma unroll
                    for (int c2 = 0; c2 < 4; c2++) {
                        float4 gq = __ldg(Gr + c2*32 + lane);
                        vv[c2*4 + 0] -= gp * gq.x;
                        vv[c2*4 + 1] -= gp * gq.y;
                        vv[c2*4 + 2] -= gp * gq.z;
                        vv[c2*4 + 3] -= gp * gq.w;
                    }
                }
                // argmax |alpha| (first-index tie-break like jnp.argmax)
                float bv = -1.f; int bk = 0;
                #pragma unroll
                for (int t = 0; t < 16; t++) {
                    int k = ((t >> 2) << 7) | (lane << 2) | (t & 3);
                    float av = fabsf(vv[t]);
                    if (av > bv) { bv = av; bk = k; }
                }
                #pragma unroll
                for (int off = 16; off > 0; off >>= 1) {
                    float ov = __shfl_xor_sync(0xffffffffu, bv, off);
                    int   ok = __shfl_xor_sync(0xffffffffu, bk, off);
                    if (ov > bv || (ov == bv && ok < bk)) { bv = ov; bk = ok; }
                }
                idx[it] = bk;
                // rhs[it] = alpha0[bk] (gather from owner lane)
                int tt = (((bk >> 7) & 3) << 2) | (bk & 3);
                float myv = sel16(a0, tt);
                rhs[it] = __shfl_sync(0xffffffffu, myv, (bk >> 2) & 31);
                // extend G_sub (uniform loads, all lanes redundant)
                #pragma unroll
                for (int b2 = 0; b2 < NNZ; b2++) if (b2 <= it) {
                    float gv = __ldg(g_G + (size_t)bk*KDIM + idx[b2]);
                    Ms[it][b2] = gv; Ms[b2][it] = gv;
                }
                // solve (it+1)x(it+1) SPD system (G_sub + eps*I) gamma = rhs
                {
                    float M[4][4], yv[4], gv2[4];
                    #pragma unroll
                    for (int r = 0; r < 4; r++) {
                        #pragma unroll
                        for (int c = 0; c < 4; c++) M[r][c] = Ms[r][c];
                        M[r][r] += REGEPS;
                        yv[r] = rhs[r];
                        gv2[r] = 0.f;
                    }
                    #pragma unroll
                    for (int c = 0; c < 4; c++) if (c <= it) {
                        float pinv = 1.f / M[c][c];
                        #pragma unroll
                        for (int r = 0; r < 4; r++) if (r > c && r <= it) {
                            float f = M[r][c] * pinv;
                            #pragma unroll
                            for (int cc = 0; cc < 4; cc++) if (cc >= c && cc <= it)
                                M[r][cc] -= f * M[c][cc];
                            yv[r] -= f * yv[c];
                        }
                    }
                    #pragma unroll
                    for (int r = 3; r >= 0; r--) if (r <= it) {
                        float a2 = yv[r];
                        #pragma unroll
                        for (int cc = 0; cc < 4; cc++) if (cc > r && cc <= it)
                            a2 -= M[r][cc] * gv2[cc];
                        gv2[r] = a2 / M[r][r];
                    }
                    #pragma unroll
                    for (int r = 0; r < 4; r++) if (r <= it) gam[r] = gv2[r];
                }
            }

            // duplicate handling: final cell value = gamma of LAST occurrence
            bool lastocc[4];
            #pragma unroll
            for (int a = 0; a < 4; a++) {
                bool lo2 = true;
                #pragma unroll
                for (int b2 = a + 1; b2 < 4; b2++) if (idx[b2] == idx[a]) lo2 = false;
                lastocc[a] = lo2;
            }

            // quant = code @ Dn^T  (DnT rows are L2-resident)
            float q0 = 0.f, q1 = 0.f;
            #pragma unroll
            for (int a = 0; a < 4; a++) if (lastocc[a]) {
                const float* dt = g_DnT + (size_t)idx[a]*DDIM;
                q0 += gam[a] * __ldg(dt + lane);
                q1 += gam[a] * __ldg(dt + lane + 32);
            }
            int n = n0 + s;
            g_qt[(size_t)n*DDIM + lane]      = q0;
            g_qt[(size_t)n*DDIM + lane + 32] = q1;
            float xv0 = ulo(xw[s*DDIM + lane]);
            float xv1 = ulo(xw[s*DDIM + lane + 32]);
            diffacc += (q0 - xv0)*(q0 - xv0) + (q1 - xv1)*(q1 - xv1);

            if (lane == 0) {
                int b = n >> 12, hw = n & 4095;
                float* ids = out + IDS_OFF + (size_t)b*(KDIM*4096) + hw;
                int cnt = 0;
                #pragma unroll
                for (int a = 0; a < 4; a++) {
                    ids[(size_t)idx[a]*4096] = gam[a];  // program order: last write wins
                    if (lastocc[a] && gam[a] != 0.f) { cnt++; zacc += fabsf(gam[a]); }
                }
                if (cnt == 0) h0++; else if (cnt == 1) h1++; else if (cnt == 2) h2++;
                else if (cnt == 3) h3++; else h4++;
            }
        }
    }

    // ---- reductions ----
    #pragma unroll
    for (int off = 16; off > 0; off >>= 1) {
        diffacc += __shfl_xor_sync(0xffffffffu, diffacc, off);
        zacc    += __shfl_xor_sync(0xffffffffu, zacc, off);
    }
    if (lane == 0) {
        atomicAdd(&sAccF[0], diffacc);
        atomicAdd(&sAccF[1], zacc);
        if (h0) atomicAdd(&sHist[0], h0);
        if (h1) atomicAdd(&sHist[1], h1);
        if (h2) atomicAdd(&sHist[2], h2);
        if (h3) atomicAdd(&sHist[3], h3);
        if (h4) atomicAdd(&sHist[4], h4);
    }
    __syncthreads();
    if (tid == 0) {
        atomicAdd(&g_diffsum, sAccF[0]);
        atomicAdd(&g_zsum, sAccF[1]);
    }
    if (tid < 5) atomicAdd(&g_hist[tid], sHist[tid]);
}

// ---------------- finalize scalars ----------------
__global__ void fin_kernel(float* __restrict__ out) {
    if (threadIdx.x != 0) return;
    float diff = g_diffsum / 2097152.0f;
    out[DIFF1_OFF] = diff;
    out[DIFF2_OFF] = diff;
    out[NSTEP_OFF] = 4.0f;
    out[MEAND_OFF] = g_meanDsum / 32768.0f;
    out[MEANZ_OFF] = g_zsum / 16777216.0f;
    int c0 = g_hist[0], c1 = g_hist[1], c2 = g_hist[2], c3 = g_hist[3], c4 = g_hist[4];
    float sumw = 1.f*c1 + 2.f*c2 + 3.f*c3 + 4.f*c4;
    out[NORMZ_OFF] = sumw / 32768.0f;
    const int topk = 327;  // int(32768 * 0.01)
    int cum = c4; float tp = 4.f;
    if (cum < topk) { cum += c3; tp = 3.f; }
    if (cum < topk) { cum += c2; tp = 2.f; }
    if (cum < topk) { cum += c1; tp = 1.f; }
    if (cum < topk) { tp = 0.f; }
    out[TOPP_OFF]  = tp;
    out[NZERO_OFF] = (float)c0;
}

// ---------------- launch ----------------
extern "C" void kernel_launch(void* const* d_in, const int* in_sizes, int n_in,
                              void* d_out, int out_size) {
    const float* x; const float* D;
    if (in_sizes[0] == DDIM*KDIM) { D = (const float*)d_in[0]; x = (const float*)d_in[1]; }
    else                          { x = (const float*)d_in[0]; D = (const float*)d_in[1]; }
    float* out = (float*)d_out;

    prep_kernel<<<1, 512>>>(D);
    gram_kernel<<<512, 128>>>();
    xt_kernel<<<dim3(128, 2, 8), dim3(32, 8)>>>(x);
    cudaMemsetAsync(out + IDS_OFF, 0, (size_t)16777216 * sizeof(float));
    cudaFuncSetAttribute(omp_kernel, cudaFuncAttributeMaxDynamicSharedMemorySize, SMEM_TOTAL);
    omp_kernel<<<152, OMP_THREADS, SMEM_TOTAL>>>(out);
    outt_kernel<<<dim3(128, 2, 8), dim3(32, 8)>>>(out);
    fin_kernel<<<1, 32>>>(out);
}

// round 5
// speedup vs baseline: 1.1680x; 1.0117x over previous
#include <cuda_runtime.h>
#include <cstdint>

#define N_SIG 32768
#define KDIM  512
#define DDIM  64
#define NNZ   4
#define REGEPS 1e-7f

// Output tuple layout (flat f32):
#define OUT_OFF   0ll         // [8,64,64,64]  = 2097152
#define DIFF1_OFF 2097152ll
#define DIFF2_OFF 2097153ll
#define IDS_OFF   2097154ll   // [8,512,64,64] = 16777216
#define NSTEP_OFF 18874370ll
#define MEAND_OFF 18874371ll
#define MEANZ_OFF 18874372ll
#define NORMZ_OFF 18874373ll
#define TOPP_OFF  18874374ll
#define NZERO_OFF 18874375ll

// ---------------- scratch (no allocation allowed) ----------------
__device__ float g_Dn[DDIM*KDIM];
__device__ float g_DnT[KDIM*DDIM];
__device__ float g_G[KDIM*KDIM];
__device__ float g_xt[(size_t)N_SIG*DDIM];
__device__ float g_qt[(size_t)N_SIG*DDIM];
__device__ float g_diffsum, g_zsum, g_meanDsum;
__device__ int   g_hist[5];

// ---------------- helpers ----------------
__device__ __forceinline__ unsigned long long ffma2(unsigned long long a,
                                                    unsigned long long b,
                                                    unsigned long long c) {
    unsigned long long d;
    asm("fma.rn.f32x2 %0, %1, %2, %3;" : "=l"(d) : "l"(a), "l"(b), "l"(c));
    return d;
}
__device__ __forceinline__ unsigned long long packdup(float v) {
    unsigned long long r;
    asm("mov.b64 %0, {%1, %1};" : "=l"(r) : "f"(v));
    return r;
}
__device__ __forceinline__ float ulo(unsigned long long u){ return __uint_as_float((unsigned)u); }
__device__ __forceinline__ float uhi(unsigned long long u){ return __uint_as_float((unsigned)(u>>32)); }

// ---------------- prep: normalize dict, build Dn / DnT, mean|Dn|, zero accs ----
__global__ void prep_kernel(const float* __restrict__ D) {
    int k = threadIdx.x;  // 512 threads
    if (k == 0) { g_diffsum = 0.f; g_zsum = 0.f; }
    if (k < 5) g_hist[k] = 0;
    float ss = 0.f;
    #pragma unroll 8
    for (int d = 0; d < DDIM; d++) { float v = D[d*KDIM + k]; ss += v*v; }
    float inv = 1.0f / sqrtf(ss);
    float asum = 0.f;
    #pragma unroll 8
    for (int d = 0; d < DDIM; d++) {
        float v = D[d*KDIM + k] * inv;
        g_Dn[d*KDIM + k] = v;
        g_DnT[k*DDIM + d] = v;
        asum += fabsf(v);
    }
    __shared__ float red[512];
    red[k] = asum; __syncthreads();
    for (int off = 256; off > 0; off >>= 1) {
        if (k < off) red[k] += red[k + off];
        __syncthreads();
    }
    if (k == 0) g_meanDsum = red[0];
}

// ---------------- Gram: G = Dn^T Dn  (smem-cached Dn, 32 blocks x 16 rows) ----
__global__ __launch_bounds__(256, 1) void gram_kernel() {
    extern __shared__ float sd[];  // 64*512 floats = 128KB
    int t = threadIdx.x;
    for (int i = t; i < DDIM*KDIM; i += 256) sd[i] = g_Dn[i];
    __syncthreads();
    int r0 = blockIdx.x * 16;
    #pragma unroll 1
    for (int jp = 0; jp < 2; jp++) {
        int j = t + jp*256;
        float a[16];
        #pragma unroll
        for (int r = 0; r < 16; r++) a[r] = 0.f;
        #pragma unroll 4
        for (int d = 0; d < DDIM; d++) {
            float cj = sd[d*KDIM + j];
            #pragma unroll
            for (int r = 0; r < 16; r++) a[r] += sd[d*KDIM + r0 + r] * cj;
        }
        #pragma unroll
        for (int r = 0; r < 16; r++) g_G[(size_t)(r0 + r)*KDIM + j] = a[r];
    }
}

// ---------------- transpose x [B,DIM,H,W] -> x_t [N,DIM] ----------------
__global__ void xt_kernel(const float* __restrict__ x) {
    __shared__ float tile[32][33];
    int b   = blockIdx.z;
    int hw0 = blockIdx.x * 32;
    int d0  = blockIdx.y * 32;
    int tx = threadIdx.x, ty = threadIdx.y;
    #pragma unroll
    for (int i = 0; i < 4; i++) {
        int d = d0 + ty + i*8;
        tile[ty + i*8][tx] = x[(size_t)(b*DDIM + d)*4096 + hw0 + tx];
    }
    __syncthreads();
    #pragma unroll
    for (int i = 0; i < 4; i++) {
        int hw = hw0 + ty + i*8;
        g_xt[(size_t)(b*4096 + hw)*DDIM + d0 + tx] = tile[tx][ty + i*8];
    }
}

// ---------------- transpose q_t [N,DIM] -> out [B,DIM,H,W] ----------------
__global__ void outt_kernel(float* __restrict__ out) {
    __shared__ float tile[32][33];
    int b   = blockIdx.z;
    int hw0 = blockIdx.x * 32;
    int d0  = blockIdx.y * 32;
    int tx = threadIdx.x, ty = threadIdx.y;
    #pragma unroll
    for (int i = 0; i < 4; i++) {
        int hw = hw0 + ty + i*8;
        tile[ty + i*8][tx] = g_qt[(size_t)(b*4096 + hw)*DDIM + d0 + tx];
    }
    __syncthreads();
    #pragma unroll
    for (int i = 0; i < 4; i++) {
        int d = d0 + ty + i*8;
        out[(size_t)(b*DDIM + d)*4096 + hw0 + tx] = tile[tx][ty + i*8];
    }
}

// ---------------- main OMP kernel ----------------
#define OMP_THREADS 512
#define OMP_WARPS   16
#define SMEM_DN_BYTES (DDIM*KDIM*4)                 // 131072
#define SMEM_X_OFF    SMEM_DN_BYTES
#define SMEM_X_BYTES  (OMP_WARPS*4*DDIM*8)          // 32768
#define SMEM_ACC_OFF  (SMEM_X_OFF + SMEM_X_BYTES)
#define SMEM_TOTAL    (SMEM_ACC_OFF + 64)

__global__ __launch_bounds__(OMP_THREADS, 1)
void omp_kernel(float* __restrict__ out) {
    extern __shared__ unsigned char smraw[];
    float* sDn = (float*)smraw;
    unsigned long long* sX = (unsigned long long*)(smraw + SMEM_X_OFF);
    float* sAccF = (float*)(smraw + SMEM_ACC_OFF);
    int*   sHist = (int*)(smraw + SMEM_ACC_OFF + 8);

    int tid  = threadIdx.x;
    int lane = tid & 31;
    int w    = tid >> 5;
    if (tid < 2) sAccF[tid] = 0.f;
    if (tid < 5) sHist[tid] = 0;
    for (int i = tid; i < DDIM*KDIM; i += OMP_THREADS) sDn[i] = g_Dn[i];
    __syncthreads();

    float diffacc = 0.f, zacc = 0.f;
    int h0 = 0, h1 = 0, h2 = 0, h3 = 0, h4 = 0;

    unsigned long long* xw = sX + w * 4 * DDIM;
    const ulonglong2* sDn2 = (const ulonglong2*)sDn;

    int gw = blockIdx.x * OMP_WARPS + w;
    int nw = gridDim.x * OMP_WARPS;
    for (int g = gw; g < N_SIG/4; g += nw) {
        int n0 = g * 4;
        __syncwarp();
        #pragma unroll
        for (int s = 0; s < 4; s++) {
            const float* xp = g_xt + (size_t)(n0 + s) * DDIM;
            xw[s*DDIM + lane]      = packdup(xp[lane]);
            xw[s*DDIM + lane + 32] = packdup(xp[lane + 32]);
        }
        __syncwarp();

        // ---- GEMV: alpha0 for 4 signals, f32x2 packed (2 k per reg) ----
        unsigned long long acc[4][8];
        #pragma unroll
        for (int s = 0; s < 4; s++)
            #pragma unroll
            for (int t = 0; t < 8; t++) acc[s][t] = 0ull;

        #pragma unroll 2
        for (int d = 0; d < DDIM; d++) {
            unsigned long long xd[4];
            #pragma unroll
            for (int s = 0; s < 4; s++) xd[s] = xw[s*DDIM + d];
            #pragma unroll
            for (int c2 = 0; c2 < 4; c2++) {
                ulonglong2 q = sDn2[d*128 + c2*32 + lane];
                #pragma unroll
                for (int s = 0; s < 4; s++) {
                    acc[s][c2*2]     = ffma2(q.x, xd[s], acc[s][c2*2]);
                    acc[s][c2*2 + 1] = ffma2(q.y, xd[s], acc[s][c2*2 + 1]);
                }
            }
        }

        // ---- OMP iterations; s fully unrolled so acc stays in registers ----
        #pragma unroll
        for (int s = 0; s < 4; s++) {
            int idx[4]; float gam[4]; float rhs[4]; float Msym[10];

            #pragma unroll
            for (int it = 0; it < NNZ; it++) {
                // current alpha = alpha0 - sum_p gam[p] * G[idx[p], :] (packed)
                unsigned long long vvp[8];
                #pragma unroll
                for (int j = 0; j < 8; j++) vvp[j] = acc[s][j];
                #pragma unroll
                for (int p = 0; p < NNZ - 1; p++) if (p < it) {
                    const ulonglong2* Gr = (const ulonglong2*)(g_G + (size_t)idx[p]*KDIM);
                    unsigned long long gneg = packdup(-gam[p]);
                    #pragma unroll
                    for (int c2 = 0; c2 < 4; c2++) {
                        ulonglong2 gq = __ldg(Gr + c2*32 + lane);
                        vvp[c2*2]     = ffma2(gq.x, gneg, vvp[c2*2]);
                        vvp[c2*2 + 1] = ffma2(gq.y, gneg, vvp[c2*2 + 1]);
                    }
                }
                // argmax |alpha| (first-index tie-break like jnp.argmax)
                float bv = -1.f; int bk = 0;
                #pragma unroll
                for (int j = 0; j < 8; j++) {
                    int c2 = j >> 1, m = (j & 1) << 1;
                    int kb = (c2 << 7) | (lane << 2) | m;
                    float alo = fabsf(ulo(vvp[j]));
                    if (alo > bv) { bv = alo; bk = kb; }
                    float ahi = fabsf(uhi(vvp[j]));
                    if (ahi > bv) { bv = ahi; bk = kb + 1; }
                }
                #pragma unroll
                for (int off = 16; off > 0; off >>= 1) {
                    float ov = __shfl_xor_sync(0xffffffffu, bv, off);
                    int   ok = __shfl_xor_sync(0xffffffffu, bk, off);
                    if (ov > bv || (ov == bv && ok < bk)) { bv = ov; bk = ok; }
                }
                idx[it] = bk;
                // rhs[it] = alpha0[bk] (gather from owner lane)
                int pj = (((bk >> 7) & 3) << 1) | ((bk >> 1) & 1);
                unsigned long long pv = acc[s][0];
                #pragma unroll
                for (int i = 1; i < 8; i++) if (pj == i) pv = acc[s][i];
                float myv = (bk & 1) ? uhi(pv) : ulo(pv);
                rhs[it] = __shfl_sync(0xffffffffu, myv, (bk >> 2) & 31);
                // extend G_sub (symmetric storage, uniform loads)
                #pragma unroll
                for (int b2 = 0; b2 < NNZ; b2++) if (b2 <= it)
                    Msym[it*(it+1)/2 + b2] = __ldg(g_G + (size_t)bk*KDIM + idx[b2]);
                // solve (it+1)x(it+1) SPD system (G_sub + eps*I) gamma = rhs
                {
                    float M[4][4], yv[4], gv2[4];
                    #pragma unroll
                    for (int r = 0; r < 4; r++) {
                        #pragma unroll
                        for (int c = 0; c < 4; c++) if (r <= it && c <= it)
                            M[r][c] = (r >= c) ? Msym[r*(r+1)/2 + c] : Msym[c*(c+1)/2 + r];
                        if (r <= it) { M[r][r] += REGEPS; yv[r] = rhs[r]; }
                        gv2[r] = 0.f;
                    }
                    #pragma unroll
                    for (int c = 0; c < 4; c++) if (c <= it) {
                        float pinv = 1.f / M[c][c];
                        #pragma unroll
                        for (int r = 0; r < 4; r++) if (r > c && r <= it) {
                            float f = M[r][c] * pinv;
                            #pragma unroll
                            for (int cc = 0; cc < 4; cc++) if (cc >= c && cc <= it)
                                M[r][cc] -= f * M[c][cc];
                            yv[r] -= f * yv[c];
                        }
                    }
                    #pragma unroll
                    for (int r = 3; r >= 0; r--) if (r <= it) {
                        float a2 = yv[r];
                        #pragma unroll
                        for (int cc = 0; cc < 4; cc++) if (cc > r && cc <= it)
                            a2 -= M[r][cc] * gv2[cc];
                        gv2[r] = a2 / M[r][r];
                    }
                    #pragma unroll
                    for (int r = 0; r < 4; r++) if (r <= it) gam[r] = gv2[r];
                }
            }

            // duplicate handling: final cell value = gamma of LAST occurrence
            bool lastocc[4];
            #pragma unroll
            for (int a = 0; a < 4; a++) {
                bool lo2 = true;
                #pragma unroll
                for (int b2 = a + 1; b2 < 4; b2++) if (idx[b2] == idx[a]) lo2 = false;
                lastocc[a] = lo2;
            }

            // quant = code @ Dn^T  (DnT rows are L2-resident)
            float q0 = 0.f, q1 = 0.f;
            #pragma unroll
            for (int a = 0; a < 4; a++) if (lastocc[a]) {
                const float* dt = g_DnT + (size_t)idx[a]*DDIM;
                q0 += gam[a] * __ldg(dt + lane);
                q1 += gam[a] * __ldg(dt + lane + 32);
            }
            int n = n0 + s;
            g_qt[(size_t)n*DDIM + lane]      = q0;
            g_qt[(size_t)n*DDIM + lane + 32] = q1;
            float xv0 = ulo(xw[s*DDIM + lane]);
            float xv1 = ulo(xw[s*DDIM + lane + 32]);
            diffacc += (q0 - xv0)*(q0 - xv0) + (q1 - xv1)*(q1 - xv1);

            if (lane == 0) {
                int b = n >> 12, hw = n & 4095;
                float* ids = out + IDS_OFF + (size_t)b*(KDIM*4096) + hw;
                int cnt = 0;
                #pragma unroll
                for (int a = 0; a < 4; a++) {
                    ids[(size_t)idx[a]*4096] = gam[a];  // program order: last write wins
                    if (lastocc[a] && gam[a] != 0.f) { cnt++; zacc += fabsf(gam[a]); }
                }
                if (cnt == 0) h0++; else if (cnt == 1) h1++; else if (cnt == 2) h2++;
                else if (cnt == 3) h3++; else h4++;
            }
        }
    }

    // ---- reductions ----
    #pragma unroll
    for (int off = 16; off > 0; off >>= 1) {
        diffacc += __shfl_xor_sync(0xffffffffu, diffacc, off);
        zacc    += __shfl_xor_sync(0xffffffffu, zacc, off);
    }
    if (lane == 0) {
        atomicAdd(&sAccF[0], diffacc);
        atomicAdd(&sAccF[1], zacc);
        if (h0) atomicAdd(&sHist[0], h0);
        if (h1) atomicAdd(&sHist[1], h1);
        if (h2) atomicAdd(&sHist[2], h2);
        if (h3) atomicAdd(&sHist[3], h3);
        if (h4) atomicAdd(&sHist[4], h4);
    }
    __syncthreads();
    if (tid == 0) {
        atomicAdd(&g_diffsum, sAccF[0]);
        atomicAdd(&g_zsum, sAccF[1]);
    }
    if (tid < 5) atomicAdd(&g_hist[tid], sHist[tid]);
}

// ---------------- finalize scalars ----------------
__global__ void fin_kernel(float* __restrict__ out) {
    if (threadIdx.x != 0) return;
    float diff = g_diffsum / 2097152.0f;
    out[DIFF1_OFF] = diff;
    out[DIFF2_OFF] = diff;
    out[NSTEP_OFF] = 4.0f;
    out[MEAND_OFF] = g_meanDsum / 32768.0f;
    out[MEANZ_OFF] = g_zsum / 16777216.0f;
    int c0 = g_hist[0], c1 = g_hist[1], c2 = g_hist[2], c3 = g_hist[3], c4 = g_hist[4];
    float sumw = 1.f*c1 + 2.f*c2 + 3.f*c3 + 4.f*c4;
    out[NORMZ_OFF] = sumw / 32768.0f;
    const int topk = 327;  // int(32768 * 0.01)
    int cum = c4; float tp = 4.f;
    if (cum < topk) { cum += c3; tp = 3.f; }
    if (cum < topk) { cum += c2; tp = 2.f; }
    if (cum < topk) { cum += c1; tp = 1.f; }
    if (cum < topk) { tp = 0.f; }
    out[TOPP_OFF]  = tp;
    out[NZERO_OFF] = (float)c0;
}

// ---------------- launch ----------------
extern "C" void kernel_launch(void* const* d_in, const int* in_sizes, int n_in,
                              void* d_out, int out_size) {
    const float* x; const float* D;
    if (in_sizes[0] == DDIM*KDIM) { D = (const float*)d_in[0]; x = (const float*)d_in[1]; }
    else                          { x = (const float*)d_in[0]; D = (const float*)d_in[1]; }
    float* out = (float*)d_out;

    prep_kernel<<<1, 512>>>(D);
    cudaFuncSetAttribute(gram_kernel, cudaFuncAttributeMaxDynamicSharedMemorySize, SMEM_DN_BYTES);
    gram_kernel<<<32, 256, SMEM_DN_BYTES>>>();
    xt_kernel<<<dim3(128, 2, 8), dim3(32, 8)>>>(x);
    cudaMemsetAsync(out + IDS_OFF, 0, (size_t)16777216 * sizeof(float));
    cudaFuncSetAttribute(omp_kernel, cudaFuncAttributeMaxDynamicSharedMemorySize, SMEM_TOTAL);
    omp_kernel<<<152, OMP_THREADS, SMEM_TOTAL>>>(out);
    outt_kernel<<<dim3(128, 2, 8), dim3(32, 8)>>>(out);
    fin_kernel<<<1, 32>>>(out);
}